// round 6
// baseline (speedup 1.0000x reference)
#include <cuda_runtime.h>
#include <cstdint>

// Problem dims (fixed)
#define BB   64
#define TT   512
#define IDIM 256
#define HH   512
#define BTH  (BB*TT*HH)

// Recurrence decomposition: 16 clusters (batch groups) x 8 CTAs (column groups)
#define GB   16
#define GC   8
#define BPG  4           // batches per group
#define CPG  64          // columns per CTA
#define NCTA (GB*GC)
#define THR  512         // threads per recurrence CTA (16 warps, 4/SMSP)

// ------------------------------ scratch ------------------------------------
__device__ float g_xb[TT*BB*HH];      // input projection, time-major [t][b][h]
__device__ float g_out0[BB*TT*HH];    // layer-0 output [b][t][h]

// ------------------------------ input GEMM ----------------------------------
#define SSTR 68

__global__ void __launch_bounds__(256) gemm_ih(
    const float* __restrict__ Xin,
    const float* __restrict__ W,
    const float* __restrict__ b1,
    const float* __restrict__ b2,
    int K, int use_g0)
{
    __shared__ float As[16 * SSTR];
    __shared__ float Bs[16 * SSTR];

    const float* X = use_g0 ? g_out0 : Xin;

    const int tid = threadIdx.x;
    const int tx  = tid & 15;
    const int ty  = tid >> 4;
    const int nb  = blockIdx.x;
    const int mb  = blockIdx.y;
    const int ar  = tid >> 2;
    const int ac  = tid & 3;

    const float* Xrow = X + (size_t)(mb * 64 + ar) * K;
    const float* Wrow = W + (size_t)(nb * 64 + ar) * K;

    float acc[4][4];
#pragma unroll
    for (int i = 0; i < 4; i++)
#pragma unroll
        for (int j = 0; j < 4; j++) acc[i][j] = 0.f;

    for (int k0 = 0; k0 < K; k0 += 16) {
        float4 av = *reinterpret_cast<const float4*>(Xrow + k0 + ac * 4);
        float4 bv = *reinterpret_cast<const float4*>(Wrow + k0 + ac * 4);
        As[(ac * 4 + 0) * SSTR + ar] = av.x;
        As[(ac * 4 + 1) * SSTR + ar] = av.y;
        As[(ac * 4 + 2) * SSTR + ar] = av.z;
        As[(ac * 4 + 3) * SSTR + ar] = av.w;
        Bs[(ac * 4 + 0) * SSTR + ar] = bv.x;
        Bs[(ac * 4 + 1) * SSTR + ar] = bv.y;
        Bs[(ac * 4 + 2) * SSTR + ar] = bv.z;
        Bs[(ac * 4 + 3) * SSTR + ar] = bv.w;
        __syncthreads();

#pragma unroll
        for (int kk = 0; kk < 16; kk++) {
            float4 a4 = *reinterpret_cast<const float4*>(&As[kk * SSTR + ty * 4]);
            float4 b4 = *reinterpret_cast<const float4*>(&Bs[kk * SSTR + tx * 4]);
            float aa[4] = {a4.x, a4.y, a4.z, a4.w};
            float bb[4] = {b4.x, b4.y, b4.z, b4.w};
#pragma unroll
            for (int i = 0; i < 4; i++)
#pragma unroll
                for (int j = 0; j < 4; j++)
                    acc[i][j] += aa[i] * bb[j];
        }
        __syncthreads();
    }

    const int n0 = nb * 64 + tx * 4;
    float4 bias;
    bias.x = b1[n0 + 0] + b2[n0 + 0];
    bias.y = b1[n0 + 1] + b2[n0 + 1];
    bias.z = b1[n0 + 2] + b2[n0 + 2];
    bias.w = b1[n0 + 3] + b2[n0 + 3];

#pragma unroll
    for (int i = 0; i < 4; i++) {
        int m  = mb * 64 + ty * 4 + i;
        int b_ = m >> 9;
        int t_ = m & (TT - 1);
        float4 o;
        o.x = acc[i][0] + bias.x;
        o.y = acc[i][1] + bias.y;
        o.z = acc[i][2] + bias.z;
        o.w = acc[i][3] + bias.w;
        *reinterpret_cast<float4*>(&g_xb[((size_t)t_ * BB + b_) * HH + n0]) = o;
    }
}

// ------------------------------ helpers -------------------------------------
__device__ __forceinline__ uint32_t smem_u32(const void* p) {
    uint32_t a;
    asm("{ .reg .u64 t; cvta.to.shared.u64 t, %1; cvt.u32.u64 %0, t; }"
        : "=r"(a) : "l"(p));
    return a;
}

__device__ __forceinline__ void mbar_wait(uint32_t mbar, uint32_t parity) {
    asm volatile(
        "{\n\t"
        ".reg .pred P;\n\t"
        "WL%=:\n\t"
        "mbarrier.try_wait.parity.acquire.cluster.shared::cta.b64 P, [%0], %1;\n\t"
        "@!P bra WL%=;\n\t"
        "}"
        :: "r"(mbar), "r"(parity) : "memory");
}

// ------------------------------ recurrence ----------------------------------
// h_{t+1}[b,c] = tanh(xb[t][b][c] + sum_k h_t[b,k] * Whh[c,k])
// Cluster of 8 CTAs per batch group. State hb[p][k] = float4 over 4 batches.
// 512 threads = 16 warps; warp w owns k-slice [32w, 32w+32) (all lanes share k
// -> broadcast h loads, 2-phase W loads). Thread tile: 2 batches x 4 cols,
// manually prefetched. k-split 16 -> red[16][256], tree-reduced by tid<256.
// Sends: scalar st.async per output (2048 x 4B per phase mbar), addresses
// hoisted; gmem writes after sends; single __syncthreads per step.
//
// smem floats: Wt[512*64] | hb[2][512]f4 | red[16][256] | mb u64[2]
#define SMF_HB   (HH*CPG)                 // 32768
#define SMF_RED  (SMF_HB + 2*HH*4)        // 36864
#define SMF_MBAR (SMF_RED + 16*256)       // 40960
#define REC_SMEM_BYTES ((SMF_MBAR + 8) * 4)

#define PHASE_TX 8192u    // 8 ranks x 256 outputs x 4B

__global__ void __launch_bounds__(THR, 1) __cluster_dims__(GC, 1, 1)
rnn_rec(const float* __restrict__ Whh,
        const float* __restrict__ h0,
        float* __restrict__ out_param,
        float* __restrict__ hn,
        int use_g0out)
{
    extern __shared__ float sm[];
    float*  Wt  = sm;                                      // [k][c]
    float4* hb  = reinterpret_cast<float4*>(sm + SMF_HB);  // [2][512]
    float*  red = sm + SMF_RED;                            // [16][256]

    const int tid = threadIdx.x;
    uint32_t cg;
    asm("mov.u32 %0, %%cluster_ctarank;" : "=r"(cg));
    const int bg  = blockIdx.x >> 3;
    const int c0  = (int)cg * CPG;
    const int b0  = bg * BPG;
    const int ks  = tid >> 5;        // warp id = K-slice 0..15 (32 k each)
    const int sub = tid & 31;
    const int cq  = sub & 15;        // column quad
    const int bh  = sub >> 4;        // batch-half: batches {2bh, 2bh+1}
    const int oc  = tid >> 2;        // (tid<256) output column 0..63
    const int ob  = tid & 3;         // (tid<256) output batch 0..3

    float* outp = use_g0out ? g_out0 : out_param;

    const uint32_t mbar_u = smem_u32(sm + SMF_MBAR);  // u64[2]: phase0, phase1
    const uint32_t hb_u   = smem_u32(hb);

    // Load W slice transposed: Wt[k][c] = Whh[c0+c][k].
    for (int idx = tid; idx < CPG * (HH / 4); idx += THR) {
        int c  = idx & (CPG - 1);
        int k4 = idx >> 6;
        float4 wv = *reinterpret_cast<const float4*>(Whh + (size_t)(c0 + c) * HH + k4 * 4);
        Wt[(k4 * 4 + 0) * CPG + c] = wv.x;
        Wt[(k4 * 4 + 1) * CPG + c] = wv.y;
        Wt[(k4 * 4 + 2) * CPG + c] = wv.z;
        Wt[(k4 * 4 + 3) * CPG + c] = wv.w;
    }
    // Init hb[0][k]: float4 over the group's 4 batches (512 threads, 1 each).
    {
        int k = tid;
        hb[k] = make_float4(h0[(size_t)(b0+0)*HH + k], h0[(size_t)(b0+1)*HH + k],
                            h0[(size_t)(b0+2)*HH + k], h0[(size_t)(b0+3)*HH + k]);
    }
    if (tid < 2) {
        uint32_t m = mbar_u + (uint32_t)tid * 8;
        asm volatile("mbarrier.init.shared.b64 [%0], %1;" :: "r"(m), "r"(1u) : "memory");
        asm volatile("mbarrier.arrive.expect_tx.shared.b64 _, [%0], %1;"
                     :: "r"(m), "r"(PHASE_TX) : "memory");
    }
    __syncthreads();
    asm volatile("barrier.cluster.arrive.aligned;" ::: "memory");
    asm volatile("barrier.cluster.wait.aligned;"   ::: "memory");

    // Hoisted remote addresses for the sender threads (tid<256).
    uint32_t da[GC], ma[GC];
    if (tid < 256) {
        const uint32_t dst_base = hb_u + (uint32_t)((c0 + oc) * 16 + ob * 4);
#pragma unroll
        for (int r = 0; r < GC; ++r) {
            asm("mapa.shared::cluster.u32 %0, %1, %2;" : "=r"(da[r]) : "r"(dst_base), "r"(r));
            asm("mapa.shared::cluster.u32 %0, %1, %2;" : "=r"(ma[r]) : "r"(mbar_u),   "r"(r));
        }
    }

    uint32_t ph[2] = {0, 0};

    for (int t = 0; t < TT; ++t) {
        const int p = t & 1;

        // Prefetch input projection (independent of h).
        float xbv = 0.f;
        if (tid < 256)
            xbv = __ldcg(&g_xb[((size_t)t * BB + (b0 + ob)) * HH + c0 + oc]);

        // Wait for this step's state.
        if (t > 0) {
            uint32_t m = mbar_u + (uint32_t)p * 8;
            mbar_wait(m, ph[p]);
            ph[p] ^= 1;
            if (tid == 0)   // re-arm for t+2 (ordered before our sends below)
                asm volatile("mbarrier.arrive.expect_tx.shared.b64 _, [%0], %1;"
                             :: "r"(m), "r"(PHASE_TX) : "memory");
        }

        // ---- FMA: 2 batches x 4 cols over warp's 32-k slice, prefetched ----
        const float2* hb2 = reinterpret_cast<const float2*>(hb + p * HH); // [2k+bh]
        const int kb = ks * 32;

        float a0x=0.f,a0y=0.f,a0z=0.f,a0w=0.f;   // batch 2bh
        float a1x=0.f,a1y=0.f,a1z=0.f,a1w=0.f;   // batch 2bh+1

        float2 hc = hb2[kb * 2 + bh];
        float4 wc = *reinterpret_cast<const float4*>(&Wt[kb * CPG + cq * 4]);
#pragma unroll
        for (int kc = 0; kc < 32; ++kc) {
            float2 hn2; float4 wn;
            if (kc < 31) {
                const int k = kb + kc + 1;
                hn2 = hb2[k * 2 + bh];
                wn  = *reinterpret_cast<const float4*>(&Wt[k * CPG + cq * 4]);
            }
            a0x += hc.x * wc.x;  a0y += hc.x * wc.y;
            a0z += hc.x * wc.z;  a0w += hc.x * wc.w;
            a1x += hc.y * wc.x;  a1y += hc.y * wc.y;
            a1z += hc.y * wc.z;  a1w += hc.y * wc.w;
            hc = hn2; wc = wn;
        }

        // Partials: red[ks][c*4 + b], c = cq*4+j, b = 2bh+{0,1} -> float2.
        {
            float* rp = &red[ks * 256 + cq * 16 + 2 * bh];
            *reinterpret_cast<float2*>(rp + 0)  = make_float2(a0x, a1x);
            *reinterpret_cast<float2*>(rp + 4)  = make_float2(a0y, a1y);
            *reinterpret_cast<float2*>(rp + 8)  = make_float2(a0z, a1z);
            *reinterpret_cast<float2*>(rp + 12) = make_float2(a0w, a1w);
        }
        __syncthreads();   // S1: all partials visible (also fences hb[p] reads)

        if (tid < 256) {
            // Tree reduce 16 partials for output o = tid.
            float r[16];
#pragma unroll
            for (int k2 = 0; k2 < 16; ++k2) r[k2] = red[k2 * 256 + tid];
#pragma unroll
            for (int s2 = 8; s2 > 0; s2 >>= 1)
#pragma unroll
                for (int i = 0; i < s2; ++i) r[i] += r[i + s2];

            float v = tanhf(r[0] + xbv);

            // Send FIRST (critical path), then gmem writes.
            if (t < TT - 1) {
                const uint32_t vb  = __float_as_uint(v);
                const uint32_t dof = (uint32_t)((p ^ 1) * 8192);
                const uint32_t mof = (uint32_t)((p ^ 1) * 8);
#pragma unroll
                for (int r8 = 0; r8 < GC; ++r8) {
                    asm volatile(
                        "st.async.shared::cluster.mbarrier::complete_tx::bytes.b32 "
                        "[%0], %1, [%2];"
                        :: "r"(da[r8] + dof), "r"(vb), "r"(ma[r8] + mof) : "memory");
                }
            }
            outp[((size_t)(b0 + ob) * TT + t) * HH + c0 + oc] = v;
            if (t == TT - 1) hn[(size_t)(b0 + ob) * HH + c0 + oc] = v;
        }
        // NO second __syncthreads: warps' t+1 mbar wait is gated by our own
        // sends (self is one of the 8 ranks), which follow the red reads.
    }

    asm volatile("barrier.cluster.arrive.aligned;" ::: "memory");
    asm volatile("barrier.cluster.wait.aligned;"   ::: "memory");
}

// ------------------------------ launch --------------------------------------
extern "C" void kernel_launch(void* const* d_in, const int* in_sizes, int n_in,
                              void* d_out, int out_size)
{
    const float* x    = (const float*)d_in[0];
    const float* h0   = (const float*)d_in[1];   // [2, B, H]
    const float* Wih0 = (const float*)d_in[2];
    const float* Whh0 = (const float*)d_in[3];
    const float* bih0 = (const float*)d_in[4];
    const float* bhh0 = (const float*)d_in[5];
    const float* Wih1 = (const float*)d_in[6];
    const float* Whh1 = (const float*)d_in[7];
    const float* bih1 = (const float*)d_in[8];
    const float* bhh1 = (const float*)d_in[9];

    float* out  = (float*)d_out;
    float* out1 = out;                       // [B,T,H]
    float* hn0  = out + (size_t)BTH;         // h_n[0]
    float* hn1  = hn0 + (size_t)BB * HH;     // h_n[1]

    static int smem_set = 0;
    if (!smem_set) {
        cudaFuncSetAttribute(rnn_rec, cudaFuncAttributeMaxDynamicSharedMemorySize,
                             REC_SMEM_BYTES);
        smem_set = 1;
    }

    dim3 ggrid(HH / 64, (BB * TT) / 64);     // (8, 512)

    gemm_ih<<<ggrid, 256>>>(x, Wih0, bih0, bhh0, IDIM, 0);
    rnn_rec<<<NCTA, THR, REC_SMEM_BYTES>>>(Whh0, h0, nullptr, hn0, 1);
    gemm_ih<<<ggrid, 256>>>(nullptr, Wih1, bih1, bhh1, HH, 1);
    rnn_rec<<<NCTA, THR, REC_SMEM_BYTES>>>(Whh1, h0 + (size_t)BB * HH, out1, hn1, 0);
}

// round 7
// speedup vs baseline: 1.0430x; 1.0430x over previous
#include <cuda_runtime.h>
#include <cstdint>

// Problem dims (fixed)
#define BB   64
#define TT   512
#define IDIM 256
#define HH   512
#define BTH  (BB*TT*HH)

// Recurrence decomposition: 16 clusters (batch groups) x 8 CTAs (column groups)
#define GB   16
#define GC   8
#define BPG  4           // batches per group
#define CPG  64          // columns per CTA
#define NCTA (GB*GC)
#define THR  256         // threads per recurrence CTA (8 warps) - best measured

typedef unsigned long long u64t;

// packed dual-fp32 FMA: d = a*b + c elementwise on f32x2
#define FMA2(d, a, b, c) \
    asm("fma.rn.f32x2 %0, %1, %2, %3;" : "=l"(d) : "l"(a), "l"(b), "l"(c))

__device__ __forceinline__ u64t pack2(float x, float y) {
    u64t r; asm("mov.b64 %0, {%1,%2};" : "=l"(r) : "f"(x), "f"(y)); return r;
}
__device__ __forceinline__ float2 unpack2(u64t v) {
    float x, y; asm("mov.b64 {%0,%1}, %2;" : "=f"(x), "=f"(y) : "l"(v));
    return make_float2(x, y);
}

// ------------------------------ scratch ------------------------------------
__device__ float g_xb[TT*BB*HH];      // input projection, time-major [t][b][h]
__device__ float g_out0[BB*TT*HH];    // layer-0 output [b][t][h]

// ------------------------------ input GEMM (FFMA2) ---------------------------
// Y[t][b][n] = sum_k X[m=(b,t)][k] * W[n][k] + b1[n] + b2[n]
// Tiles 64x64x16, 4x4 per thread. A staged DUPLICATED in smem so a-pairs
// (a_i, a_i) load directly; B float4 = natural packed column pairs.
#define SSTR 68
#define ADSTR 132    // duplicated A row: 128 floats + pad (132*4B = 16B-aligned rows)

__global__ void __launch_bounds__(256) gemm_ih(
    const float* __restrict__ Xin,
    const float* __restrict__ W,
    const float* __restrict__ b1,
    const float* __restrict__ b2,
    int K, int use_g0)
{
    __shared__ float Asd[16 * ADSTR];   // [kk][2m] duplicated
    __shared__ float Bs[16 * SSTR];

    const float* X = use_g0 ? g_out0 : Xin;

    const int tid = threadIdx.x;
    const int tx  = tid & 15;
    const int ty  = tid >> 4;
    const int nb  = blockIdx.x;
    const int mb  = blockIdx.y;
    const int ar  = tid >> 2;
    const int ac  = tid & 3;

    const float* Xrow = X + (size_t)(mb * 64 + ar) * K;
    const float* Wrow = W + (size_t)(nb * 64 + ar) * K;

    u64t acc2[4][2];
#pragma unroll
    for (int i = 0; i < 4; i++) { acc2[i][0] = 0ull; acc2[i][1] = 0ull; }

    for (int k0 = 0; k0 < K; k0 += 16) {
        float4 av = *reinterpret_cast<const float4*>(Xrow + k0 + ac * 4);
        float4 bv = *reinterpret_cast<const float4*>(Wrow + k0 + ac * 4);
        // duplicated A stores: Asd[k][2m] = Asd[k][2m+1] = a
        {
            float* p0 = &Asd[(ac * 4 + 0) * ADSTR + ar * 2];
            float* p1 = &Asd[(ac * 4 + 1) * ADSTR + ar * 2];
            float* p2 = &Asd[(ac * 4 + 2) * ADSTR + ar * 2];
            float* p3 = &Asd[(ac * 4 + 3) * ADSTR + ar * 2];
            p0[0] = av.x; p0[1] = av.x;
            p1[0] = av.y; p1[1] = av.y;
            p2[0] = av.z; p2[1] = av.z;
            p3[0] = av.w; p3[1] = av.w;
        }
        Bs[(ac * 4 + 0) * SSTR + ar] = bv.x;
        Bs[(ac * 4 + 1) * SSTR + ar] = bv.y;
        Bs[(ac * 4 + 2) * SSTR + ar] = bv.z;
        Bs[(ac * 4 + 3) * SSTR + ar] = bv.w;
        __syncthreads();

#pragma unroll
        for (int kk = 0; kk < 16; kk++) {
            ulonglong2 a01 = *reinterpret_cast<const ulonglong2*>(&Asd[kk * ADSTR + ty * 8]);
            ulonglong2 a23 = *reinterpret_cast<const ulonglong2*>(&Asd[kk * ADSTR + ty * 8 + 4]);
            ulonglong2 bw  = *reinterpret_cast<const ulonglong2*>(&Bs[kk * SSTR + tx * 4]);
            FMA2(acc2[0][0], a01.x, bw.x, acc2[0][0]);
            FMA2(acc2[0][1], a01.x, bw.y, acc2[0][1]);
            FMA2(acc2[1][0], a01.y, bw.x, acc2[1][0]);
            FMA2(acc2[1][1], a01.y, bw.y, acc2[1][1]);
            FMA2(acc2[2][0], a23.x, bw.x, acc2[2][0]);
            FMA2(acc2[2][1], a23.x, bw.y, acc2[2][1]);
            FMA2(acc2[3][0], a23.y, bw.x, acc2[3][0]);
            FMA2(acc2[3][1], a23.y, bw.y, acc2[3][1]);
        }
        __syncthreads();
    }

    const int n0 = nb * 64 + tx * 4;
    float4 bias;
    bias.x = b1[n0 + 0] + b2[n0 + 0];
    bias.y = b1[n0 + 1] + b2[n0 + 1];
    bias.z = b1[n0 + 2] + b2[n0 + 2];
    bias.w = b1[n0 + 3] + b2[n0 + 3];

#pragma unroll
    for (int i = 0; i < 4; i++) {
        int m  = mb * 64 + ty * 4 + i;
        int b_ = m >> 9;
        int t_ = m & (TT - 1);
        float2 lo = unpack2(acc2[i][0]);
        float2 hi = unpack2(acc2[i][1]);
        float4 o;
        o.x = lo.x + bias.x;
        o.y = lo.y + bias.y;
        o.z = hi.x + bias.z;
        o.w = hi.y + bias.w;
        *reinterpret_cast<float4*>(&g_xb[((size_t)t_ * BB + b_) * HH + n0]) = o;
    }
}

// ------------------------------ helpers -------------------------------------
__device__ __forceinline__ uint32_t smem_u32(const void* p) {
    uint32_t a;
    asm("{ .reg .u64 t; cvta.to.shared.u64 t, %1; cvt.u32.u64 %0, t; }"
        : "=r"(a) : "l"(p));
    return a;
}

__device__ __forceinline__ void mbar_wait(uint32_t mbar, uint32_t parity) {
    asm volatile(
        "{\n\t"
        ".reg .pred P;\n\t"
        "WL%=:\n\t"
        "mbarrier.try_wait.parity.acquire.cluster.shared::cta.b64 P, [%0], %1;\n\t"
        "@!P bra WL%=;\n\t"
        "}"
        :: "r"(mbar), "r"(parity) : "memory");
}

// ------------------------------ recurrence ----------------------------------
// h_{t+1}[b,c] = tanh(xb[t][b][c] + sum_k h_t[b,k] * Whh[c,k])
// R3 skeleton (256 thr, scalar st.async, 2 phase mbars) with FFMA2 compute:
// hidden state stored DUPLICATED: hd[p][k] = [h0,h0,h1,h1,h2,h2,h3,h3] (32B).
// Senders push (v,v) via st.async.b64 to all 8 cluster CTAs.
// Inner loop per k: 3x LDS.128 + 8x FFMA2 (was 2 LDS + 16 FFMA).
//
// smem floats: Wt[512*64] | hd[2][512*8] | red[16][256] | mb u64[2]
#define SMF_HD   (HH*CPG)                 // 32768
#define SMF_RED  (SMF_HD + 2*HH*8)        // 40960
#define SMF_MBAR (SMF_RED + 16*256)       // 45056
#define REC_SMEM_BYTES ((SMF_MBAR + 8) * 4)

#define PHASE_TX 16384u    // 8 ranks x 256 outputs x 8B

__global__ void __launch_bounds__(THR, 1) __cluster_dims__(GC, 1, 1)
rnn_rec(const float* __restrict__ Whh,
        const float* __restrict__ h0,
        float* __restrict__ out_param,
        float* __restrict__ hn,
        int use_g0out)
{
    extern __shared__ float sm[];
    float* Wt = sm;                                             // [k][c]
    ulonglong2* hd = reinterpret_cast<ulonglong2*>(sm + SMF_HD); // [2][512*2]
    float* red = sm + SMF_RED;                                  // [16][256]

    const int tid = threadIdx.x;
    uint32_t cg;
    asm("mov.u32 %0, %%cluster_ctarank;" : "=r"(cg));
    const int bg  = blockIdx.x >> 3;
    const int c0  = (int)cg * CPG;
    const int b0  = bg * BPG;
    const int ks  = tid >> 4;        // K-slice 0..15 (32 k each)
    const int cq  = tid & 15;        // column quad
    const int oc  = tid >> 2;        // output column 0..63
    const int ob  = tid & 3;         // output batch 0..3

    float* outp = use_g0out ? g_out0 : out_param;

    const uint32_t mbar_u = smem_u32(sm + SMF_MBAR);  // u64[2]: phase0, phase1
    const uint32_t hd_u   = smem_u32(hd);

    // Load W slice transposed: Wt[k][c] = Whh[c0+c][k].
    for (int idx = tid; idx < CPG * (HH / 4); idx += THR) {
        int c  = idx & (CPG - 1);
        int k4 = idx >> 6;
        float4 wv = *reinterpret_cast<const float4*>(Whh + (size_t)(c0 + c) * HH + k4 * 4);
        Wt[(k4 * 4 + 0) * CPG + c] = wv.x;
        Wt[(k4 * 4 + 1) * CPG + c] = wv.y;
        Wt[(k4 * 4 + 2) * CPG + c] = wv.z;
        Wt[(k4 * 4 + 3) * CPG + c] = wv.w;
    }
    // Init hd[0][k]: duplicated 4-batch row.
#pragma unroll
    for (int r = 0; r < 2; ++r) {
        int k = tid + r * 256;
        float h0v = h0[(size_t)(b0 + 0) * HH + k];
        float h1v = h0[(size_t)(b0 + 1) * HH + k];
        float h2v = h0[(size_t)(b0 + 2) * HH + k];
        float h3v = h0[(size_t)(b0 + 3) * HH + k];
        hd[k * 2 + 0] = make_ulonglong2(pack2(h0v, h0v), pack2(h1v, h1v));
        hd[k * 2 + 1] = make_ulonglong2(pack2(h2v, h2v), pack2(h3v, h3v));
    }
    if (tid < 2) {
        uint32_t m = mbar_u + (uint32_t)tid * 8;
        asm volatile("mbarrier.init.shared.b64 [%0], %1;" :: "r"(m), "r"(1u) : "memory");
        asm volatile("mbarrier.arrive.expect_tx.shared.b64 _, [%0], %1;"
                     :: "r"(m), "r"(PHASE_TX) : "memory");
    }
    __syncthreads();
    asm volatile("barrier.cluster.arrive.aligned;" ::: "memory");
    asm volatile("barrier.cluster.wait.aligned;"   ::: "memory");

    uint32_t ph[2] = {0, 0};

    for (int t = 0; t < TT; ++t) {
        const int p = t & 1;

        // Prefetch input projection (independent of h).
        float xbv = __ldcg(&g_xb[((size_t)t * BB + (b0 + ob)) * HH + c0 + oc]);

        // Wait for this step's state.
        if (t > 0) {
            uint32_t m = mbar_u + (uint32_t)p * 8;
            mbar_wait(m, ph[p]);
            ph[p] ^= 1;
            if (tid == 0)   // re-arm for t+2 (our sends below gate peers)
                asm volatile("mbarrier.arrive.expect_tx.shared.b64 _, [%0], %1;"
                             :: "r"(m), "r"(PHASE_TX) : "memory");
        }

        const ulonglong2* hdp = hd + p * (HH * 2);

        // 4 batches x 4 cols: 8 packed accumulators over 32-k slice.
        u64t acc2[4][2];
#pragma unroll
        for (int b = 0; b < 4; b++) { acc2[b][0] = 0ull; acc2[b][1] = 0ull; }

        const int kb = ks * 32;
#pragma unroll 8
        for (int kc = 0; kc < 32; ++kc) {
            const int k = kb + kc;
            ulonglong2 h01 = hdp[k * 2 + 0];   // (h0,h0),(h1,h1)
            ulonglong2 h23 = hdp[k * 2 + 1];   // (h2,h2),(h3,h3)
            ulonglong2 w2  = *reinterpret_cast<const ulonglong2*>(&Wt[k * CPG + cq * 4]);
            FMA2(acc2[0][0], h01.x, w2.x, acc2[0][0]);
            FMA2(acc2[0][1], h01.x, w2.y, acc2[0][1]);
            FMA2(acc2[1][0], h01.y, w2.x, acc2[1][0]);
            FMA2(acc2[1][1], h01.y, w2.y, acc2[1][1]);
            FMA2(acc2[2][0], h23.x, w2.x, acc2[2][0]);
            FMA2(acc2[2][1], h23.x, w2.y, acc2[2][1]);
            FMA2(acc2[3][0], h23.y, w2.x, acc2[3][0]);
            FMA2(acc2[3][1], h23.y, w2.y, acc2[3][1]);
        }

        // Unpack -> red[ks][o], o = cq*16 + j*4 + b.
        {
            float a[4][4];
#pragma unroll
            for (int b = 0; b < 4; ++b) {
                float2 lo = unpack2(acc2[b][0]);
                float2 hi = unpack2(acc2[b][1]);
                a[b][0] = lo.x; a[b][1] = lo.y; a[b][2] = hi.x; a[b][3] = hi.y;
            }
#pragma unroll
            for (int j = 0; j < 4; ++j)
                *reinterpret_cast<float4*>(&red[ks * 256 + cq * 16 + j * 4]) =
                    make_float4(a[0][j], a[1][j], a[2][j], a[3][j]);
        }
        __syncthreads();   // S1

        // Tree reduce 16 partials for output o = tid, add xb, tanh.
        float r[16];
#pragma unroll
        for (int k2 = 0; k2 < 16; ++k2) r[k2] = red[k2 * 256 + tid];
#pragma unroll
        for (int s2 = 8; s2 > 0; s2 >>= 1)
#pragma unroll
            for (int i = 0; i < s2; ++i) r[i] += r[i + s2];

        float v = tanhf(r[0] + xbv);

        // Send (v,v) to all 8 cluster CTAs' next-phase duplicated slot.
        if (t < TT - 1) {
            const u64t vv = pack2(v, v);
            const uint32_t dst_l = hd_u + (uint32_t)((p ^ 1) * 16384)
                                 + (uint32_t)((c0 + oc) * 32 + ob * 8);
            const uint32_t mbr_l = mbar_u + (uint32_t)((p ^ 1) * 8);
#pragma unroll
            for (int r8 = 0; r8 < GC; ++r8) {
                uint32_t da, ma;
                asm("mapa.shared::cluster.u32 %0, %1, %2;" : "=r"(da) : "r"(dst_l), "r"(r8));
                asm("mapa.shared::cluster.u32 %0, %1, %2;" : "=r"(ma) : "r"(mbr_l), "r"(r8));
                asm volatile(
                    "st.async.shared::cluster.mbarrier::complete_tx::bytes.b64 [%0], %1, [%2];"
                    :: "r"(da), "l"(vv), "r"(ma) : "memory");
            }
        }

        // Outputs to gmem (off the sync critical path).
        outp[((size_t)(b0 + ob) * TT + t) * HH + c0 + oc] = v;
        if (t == TT - 1) hn[(size_t)(b0 + ob) * HH + c0 + oc] = v;

        __syncthreads();   // close red read-vs-write for next step
    }

    asm volatile("barrier.cluster.arrive.aligned;" ::: "memory");
    asm volatile("barrier.cluster.wait.aligned;"   ::: "memory");
}

// ------------------------------ launch --------------------------------------
extern "C" void kernel_launch(void* const* d_in, const int* in_sizes, int n_in,
                              void* d_out, int out_size)
{
    const float* x    = (const float*)d_in[0];
    const float* h0   = (const float*)d_in[1];   // [2, B, H]
    const float* Wih0 = (const float*)d_in[2];
    const float* Whh0 = (const float*)d_in[3];
    const float* bih0 = (const float*)d_in[4];
    const float* bhh0 = (const float*)d_in[5];
    const float* Wih1 = (const float*)d_in[6];
    const float* Whh1 = (const float*)d_in[7];
    const float* bih1 = (const float*)d_in[8];
    const float* bhh1 = (const float*)d_in[9];

    float* out  = (float*)d_out;
    float* out1 = out;                       // [B,T,H]
    float* hn0  = out + (size_t)BTH;         // h_n[0]
    float* hn1  = hn0 + (size_t)BB * HH;     // h_n[1]

    static int smem_set = 0;
    if (!smem_set) {
        cudaFuncSetAttribute(rnn_rec, cudaFuncAttributeMaxDynamicSharedMemorySize,
                             REC_SMEM_BYTES);
        smem_set = 1;
    }

    dim3 ggrid(HH / 64, (BB * TT) / 64);     // (8, 512)

    gemm_ih<<<ggrid, 256>>>(x, Wih0, bih0, bhh0, IDIM, 0);
    rnn_rec<<<NCTA, THR, REC_SMEM_BYTES>>>(Whh0, h0, nullptr, hn0, 1);
    gemm_ih<<<ggrid, 256>>>(nullptr, Wih1, bih1, bhh1, HH, 1);
    rnn_rec<<<NCTA, THR, REC_SMEM_BYTES>>>(Whh1, h0 + (size_t)BB * HH, out1, hn1, 0);
}

// round 8
// speedup vs baseline: 1.3035x; 1.2498x over previous
#include <cuda_runtime.h>
#include <cstdint>

// Problem dims (fixed)
#define BB   64
#define TT   512
#define IDIM 256
#define HH   512
#define BTH  (BB*TT*HH)

// Recurrence decomposition: 16 clusters (batch groups) x 8 CTAs (column groups)
#define GB   16
#define GC   8
#define BPG  4           // batches per group
#define CPG  64          // columns per CTA
#define NCTA (GB*GC)
#define THR  512         // 16 warps: 4/SMSP for latency hiding; W held in regs

// ------------------------------ scratch ------------------------------------
__device__ float g_xb[TT*BB*HH];      // input projection, time-major [t][b][h]
__device__ float g_out0[BB*TT*HH];    // layer-0 output [b][t][h]

// ------------------------------ input GEMM (proven R1 version) ---------------
#define SSTR 68

__global__ void __launch_bounds__(256) gemm_ih(
    const float* __restrict__ Xin,
    const float* __restrict__ W,
    const float* __restrict__ b1,
    const float* __restrict__ b2,
    int K, int use_g0)
{
    __shared__ float As[16 * SSTR];
    __shared__ float Bs[16 * SSTR];

    const float* X = use_g0 ? g_out0 : Xin;

    const int tid = threadIdx.x;
    const int tx  = tid & 15;
    const int ty  = tid >> 4;
    const int nb  = blockIdx.x;
    const int mb  = blockIdx.y;
    const int ar  = tid >> 2;
    const int ac  = tid & 3;

    const float* Xrow = X + (size_t)(mb * 64 + ar) * K;
    const float* Wrow = W + (size_t)(nb * 64 + ar) * K;

    float acc[4][4];
#pragma unroll
    for (int i = 0; i < 4; i++)
#pragma unroll
        for (int j = 0; j < 4; j++) acc[i][j] = 0.f;

    for (int k0 = 0; k0 < K; k0 += 16) {
        float4 av = *reinterpret_cast<const float4*>(Xrow + k0 + ac * 4);
        float4 bv = *reinterpret_cast<const float4*>(Wrow + k0 + ac * 4);
        As[(ac * 4 + 0) * SSTR + ar] = av.x;
        As[(ac * 4 + 1) * SSTR + ar] = av.y;
        As[(ac * 4 + 2) * SSTR + ar] = av.z;
        As[(ac * 4 + 3) * SSTR + ar] = av.w;
        Bs[(ac * 4 + 0) * SSTR + ar] = bv.x;
        Bs[(ac * 4 + 1) * SSTR + ar] = bv.y;
        Bs[(ac * 4 + 2) * SSTR + ar] = bv.z;
        Bs[(ac * 4 + 3) * SSTR + ar] = bv.w;
        __syncthreads();

#pragma unroll
        for (int kk = 0; kk < 16; kk++) {
            float4 a4 = *reinterpret_cast<const float4*>(&As[kk * SSTR + ty * 4]);
            float4 b4 = *reinterpret_cast<const float4*>(&Bs[kk * SSTR + tx * 4]);
            float aa[4] = {a4.x, a4.y, a4.z, a4.w};
            float bb[4] = {b4.x, b4.y, b4.z, b4.w};
#pragma unroll
            for (int i = 0; i < 4; i++)
#pragma unroll
                for (int j = 0; j < 4; j++)
                    acc[i][j] += aa[i] * bb[j];
        }
        __syncthreads();
    }

    const int n0 = nb * 64 + tx * 4;
    float4 bias;
    bias.x = b1[n0 + 0] + b2[n0 + 0];
    bias.y = b1[n0 + 1] + b2[n0 + 1];
    bias.z = b1[n0 + 2] + b2[n0 + 2];
    bias.w = b1[n0 + 3] + b2[n0 + 3];

#pragma unroll
    for (int i = 0; i < 4; i++) {
        int m  = mb * 64 + ty * 4 + i;
        int b_ = m >> 9;
        int t_ = m & (TT - 1);
        float4 o;
        o.x = acc[i][0] + bias.x;
        o.y = acc[i][1] + bias.y;
        o.z = acc[i][2] + bias.z;
        o.w = acc[i][3] + bias.w;
        *reinterpret_cast<float4*>(&g_xb[((size_t)t_ * BB + b_) * HH + n0]) = o;
    }
}

// ------------------------------ helpers -------------------------------------
__device__ __forceinline__ uint32_t smem_u32(const void* p) {
    uint32_t a;
    asm("{ .reg .u64 t; cvta.to.shared.u64 t, %1; cvt.u32.u64 %0, t; }"
        : "=r"(a) : "l"(p));
    return a;
}

__device__ __forceinline__ void mbar_wait(uint32_t mbar, uint32_t parity) {
    asm volatile(
        "{\n\t"
        ".reg .pred P;\n\t"
        "WL%=:\n\t"
        "mbarrier.try_wait.parity.acquire.cluster.shared::cta.b64 P, [%0], %1;\n\t"
        "@!P bra WL%=;\n\t"
        "}"
        :: "r"(mbar), "r"(parity) : "memory");
}

// ------------------------------ recurrence ----------------------------------
// h_{t+1}[b,c] = tanh(xb[t][b][c] + sum_k h_t[b,k] * Whh[c,k])
// Cluster of 8 CTAs per batch group. KEY CHANGE vs R3: the 128KB W slice is
// held in REGISTERS (thread (ks=tid>>6, c=tid&63) keeps W[c0+c][64ks..64ks+64)
// as float4 W4[16]); per-step smem reads are only h broadcasts (~17KB/step vs
// ~170KB). k-split 8 -> red[8][256]; ONE __syncthreads per step (post-reduce
// barrier is redundant: passing the t+1 mbar wait implies this CTA's sends --
// which data-depend on the red reads -- completed). Transport: R3's scalar
// st.async x8 ranks + 2 phase mbarriers.
#define HROW 520                       // padded h row (floats), 16B-multiple
#define HB_F (BPG*HROW)                // 2080 floats per phase
#define PHASE_TX 8192u                 // 8 ranks x 256 outputs x 4B

__global__ void __launch_bounds__(THR, 1) __cluster_dims__(GC, 1, 1)
rnn_rec(const float* __restrict__ Whh,
        const float* __restrict__ h0,
        float* __restrict__ out_param,
        float* __restrict__ hn,
        int use_g0out)
{
    __shared__ float hbf[2 * HB_F];          // h state, [p][b][HROW]
    __shared__ float red[8 * 256];           // k-split partials
    __shared__ unsigned long long mbars[2];  // phase mbarriers

    const int tid = threadIdx.x;
    uint32_t cg;
    asm("mov.u32 %0, %%cluster_ctarank;" : "=r"(cg));
    const int bg = blockIdx.x >> 3;
    const int c0 = (int)cg * CPG;
    const int b0 = bg * BPG;
    const int ks = tid >> 6;         // k-slice 0..7 (64 k each)
    const int c  = tid & 63;         // local column 0..63
    const int ob = tid >> 6;         // (senders tid<256) -- NOTE: use tid<256 view:
    const int oc = tid & 63;         //   ob = tid>>6 in 0..3, oc = tid&63

    float* outp = use_g0out ? g_out0 : out_param;

    const uint32_t mbar_u = smem_u32(mbars);
    const uint32_t hb_u   = smem_u32(hbf);

    // ---- Load this thread's W slice into registers (once) ----
    float4 W4[16];
    {
        const float* wrow = Whh + (size_t)(c0 + c) * HH + ks * 64;
#pragma unroll
        for (int kq = 0; kq < 16; ++kq)
            W4[kq] = *reinterpret_cast<const float4*>(wrow + kq * 4);
    }

    // ---- Init h state, phase 0: hbf[b][k] = h0[b0+b][k] ----
    {
        int b  = tid >> 7;           // 0..3
        int kq = tid & 127;          // 0..127
        *reinterpret_cast<float4*>(&hbf[b * HROW + kq * 4]) =
            *reinterpret_cast<const float4*>(&h0[(size_t)(b0 + b) * HH + kq * 4]);
    }
    if (tid < 2) {
        uint32_t m = mbar_u + (uint32_t)tid * 8;
        asm volatile("mbarrier.init.shared.b64 [%0], %1;" :: "r"(m), "r"(1u) : "memory");
        asm volatile("mbarrier.arrive.expect_tx.shared.b64 _, [%0], %1;"
                     :: "r"(m), "r"(PHASE_TX) : "memory");
    }
    __syncthreads();
    asm volatile("barrier.cluster.arrive.aligned;" ::: "memory");
    asm volatile("barrier.cluster.wait.aligned;"   ::: "memory");

    uint32_t ph[2] = {0, 0};

    for (int t = 0; t < TT; ++t) {
        const int p = t & 1;

        // Prefetch input projection (independent of h).
        float xbv = 0.f;
        if (tid < 256)
            xbv = __ldcg(&g_xb[((size_t)t * BB + (b0 + ob)) * HH + c0 + oc]);

        // Wait for this step's state.
        if (t > 0) {
            uint32_t m = mbar_u + (uint32_t)p * 8;
            mbar_wait(m, ph[p]);
            ph[p] ^= 1;
            if (tid == 0)   // re-arm for t+2 (program-order before our sends)
                asm volatile("mbarrier.arrive.expect_tx.shared.b64 _, [%0], %1;"
                             :: "r"(m), "r"(PHASE_TX) : "memory");
        }

        // ---- FMA: W from registers, h broadcast from smem ----
        const float* hp = hbf + p * HB_F + ks * 64;   // + b*HROW per batch
        float4 A0 = make_float4(0.f,0.f,0.f,0.f);
        float4 A1 = A0, A2 = A0, A3 = A0;
#pragma unroll
        for (int kq = 0; kq < 16; ++kq) {
            float4 w  = W4[kq];
            float4 h0v = *reinterpret_cast<const float4*>(hp + 0 * HROW + kq * 4);
            float4 h1v = *reinterpret_cast<const float4*>(hp + 1 * HROW + kq * 4);
            float4 h2v = *reinterpret_cast<const float4*>(hp + 2 * HROW + kq * 4);
            float4 h3v = *reinterpret_cast<const float4*>(hp + 3 * HROW + kq * 4);
            A0.x += w.x * h0v.x; A0.y += w.y * h0v.y; A0.z += w.z * h0v.z; A0.w += w.w * h0v.w;
            A1.x += w.x * h1v.x; A1.y += w.y * h1v.y; A1.z += w.z * h1v.z; A1.w += w.w * h1v.w;
            A2.x += w.x * h2v.x; A2.y += w.y * h2v.y; A2.z += w.z * h2v.z; A2.w += w.w * h2v.w;
            A3.x += w.x * h3v.x; A3.y += w.y * h3v.y; A3.z += w.z * h3v.z; A3.w += w.w * h3v.w;
        }

        // Partials -> red[ks][c*4 + b] (one float4 per thread).
        *reinterpret_cast<float4*>(&red[ks * 256 + c * 4]) =
            make_float4((A0.x + A0.y) + (A0.z + A0.w),
                        (A1.x + A1.y) + (A1.z + A1.w),
                        (A2.x + A2.y) + (A2.z + A2.w),
                        (A3.x + A3.y) + (A3.z + A3.w));
        __syncthreads();   // S1: all partials visible

        if (tid < 256) {
            const int o = oc * 4 + ob;   // red column for output (oc, ob)
            float r0 = red[0*256 + o] + red[1*256 + o];
            float r1 = red[2*256 + o] + red[3*256 + o];
            float r2 = red[4*256 + o] + red[5*256 + o];
            float r3 = red[6*256 + o] + red[7*256 + o];
            float v  = tanhf(((r0 + r1) + (r2 + r3)) + xbv);

            // Send to all 8 cluster CTAs' next-phase h buffer (critical path).
            if (t < TT - 1) {
                const uint32_t vb    = __float_as_uint(v);
                const uint32_t dst_l = hb_u + (uint32_t)((p ^ 1) * (HB_F * 4))
                                     + (uint32_t)((ob * HROW + c0 + oc) * 4);
                const uint32_t mbr_l = mbar_u + (uint32_t)((p ^ 1) * 8);
#pragma unroll
                for (int r8 = 0; r8 < GC; ++r8) {
                    uint32_t da, ma;
                    asm("mapa.shared::cluster.u32 %0, %1, %2;" : "=r"(da) : "r"(dst_l), "r"(r8));
                    asm("mapa.shared::cluster.u32 %0, %1, %2;" : "=r"(ma) : "r"(mbr_l), "r"(r8));
                    asm volatile(
                        "st.async.shared::cluster.mbarrier::complete_tx::bytes.b32 [%0], %1, [%2];"
                        :: "r"(da), "r"(vb), "r"(ma) : "memory");
                }
            }

            // Outputs to gmem (coalesced: warp = 32 consecutive oc).
            outp[((size_t)(b0 + ob) * TT + t) * HH + c0 + oc] = v;
            if (t == TT - 1) hn[(size_t)(b0 + ob) * HH + c0 + oc] = v;
        }
        // No second barrier: red reuse at t+1 is gated by the t+1 mbar wait,
        // which requires our sends, which data-depend on the red reads above.
    }

    asm volatile("barrier.cluster.arrive.aligned;" ::: "memory");
    asm volatile("barrier.cluster.wait.aligned;"   ::: "memory");
}

// ------------------------------ launch --------------------------------------
extern "C" void kernel_launch(void* const* d_in, const int* in_sizes, int n_in,
                              void* d_out, int out_size)
{
    const float* x    = (const float*)d_in[0];
    const float* h0   = (const float*)d_in[1];   // [2, B, H]
    const float* Wih0 = (const float*)d_in[2];
    const float* Whh0 = (const float*)d_in[3];
    const float* bih0 = (const float*)d_in[4];
    const float* bhh0 = (const float*)d_in[5];
    const float* Wih1 = (const float*)d_in[6];
    const float* Whh1 = (const float*)d_in[7];
    const float* bih1 = (const float*)d_in[8];
    const float* bhh1 = (const float*)d_in[9];

    float* out  = (float*)d_out;
    float* out1 = out;                       // [B,T,H]
    float* hn0  = out + (size_t)BTH;         // h_n[0]
    float* hn1  = hn0 + (size_t)BB * HH;     // h_n[1]

    dim3 ggrid(HH / 64, (BB * TT) / 64);     // (8, 512)

    gemm_ih<<<ggrid, 256>>>(x, Wih0, bih0, bhh0, IDIM, 0);
    rnn_rec<<<NCTA, THR>>>(Whh0, h0, nullptr, hn0, 1);
    gemm_ih<<<ggrid, 256>>>(nullptr, Wih1, bih1, bhh1, HH, 1);
    rnn_rec<<<NCTA, THR>>>(Whh1, h0 + (size_t)BB * HH, out1, hn1, 0);
}

// round 9
// speedup vs baseline: 1.6338x; 1.2534x over previous
#include <cuda_runtime.h>
#include <cuda_bf16.h>
#include <mma.h>
#include <cstdint>

using namespace nvcuda;

// Problem dims (fixed)
#define BB   64
#define TT   512
#define IDIM 256
#define HH   512
#define BTH  (BB*TT*HH)

// Recurrence decomposition: 16 clusters (batch groups) x 8 CTAs (column groups)
#define GB   16
#define GC   8
#define BPG  4           // batches per group
#define CPG  64          // columns per CTA
#define NCTA (GB*GC)
#define THR  256         // threads per recurrence CTA (best measured: R3)

// ------------------------------ scratch ------------------------------------
__device__ float g_xb[TT*BB*HH];              // input projection [t][b][h]
__device__ float g_out0[BB*TT*HH];            // layer-0 output [b][t][h]
__device__ __nv_bfloat16 g_ahi[BTH];          // split activations (hi)
__device__ __nv_bfloat16 g_alo[BTH];          // split activations (lo)
__device__ __nv_bfloat16 g_whi[HH*HH];        // split weights (hi)
__device__ __nv_bfloat16 g_wlo[HH*HH];        // split weights (lo)

// ------------------------------ split conversion -----------------------------
__global__ void conv_split(const float* __restrict__ s,
                           __nv_bfloat16* __restrict__ hi,
                           __nv_bfloat16* __restrict__ lo, int n)
{
    int i = blockIdx.x * blockDim.x + threadIdx.x;
    if (i < n) {
        float x = s[i];
        __nv_bfloat16 h = __float2bfloat16_rn(x);
        hi[i] = h;
        lo[i] = __float2bfloat16_rn(x - __bfloat162float(h));
    }
}

// ------------------------------ wmma GEMM (bf16 x3 split) --------------------
// Y[t][b][n] = sum_k A[m][k]*W[n][k] + b1[n] + b2[n],  m = b*TT + t
// A = Ah+Al (bf16 split), W = Bh+Bl. 3 cross terms, fp32 accum.
// CTA tile 64(m) x 64(n), K-chunks of 64. 8 warps: (wr 0..3) x (wc 0..1),
// each warp computes 16(m) x 32(n) via two 16x16 accum fragments.
#define KC   64
#define LDS2 72          // smem tile leading dim (bf16 elems)

__global__ void __launch_bounds__(256) gemm_wmma(
    const __nv_bfloat16* __restrict__ Ah, const __nv_bfloat16* __restrict__ Al,
    const __nv_bfloat16* __restrict__ Bh, const __nv_bfloat16* __restrict__ Bl,
    const float* __restrict__ b1, const float* __restrict__ b2, int K)
{
    __shared__ char raw[4 * 64 * LDS2 * 2];   // 36864 B
    __nv_bfloat16* sAh = reinterpret_cast<__nv_bfloat16*>(raw);
    __nv_bfloat16* sAl = sAh + 64 * LDS2;
    __nv_bfloat16* sBh = sAl + 64 * LDS2;
    __nv_bfloat16* sBl = sBh + 64 * LDS2;

    const int tid = threadIdx.x;
    const int nb  = blockIdx.x;
    const int mb  = blockIdx.y;
    const int wid = tid >> 5;
    const int wr  = wid & 3;        // m-subtile 0..3
    const int wc  = wid >> 2;       // n-half 0..1

    wmma::fragment<wmma::accumulator, 16, 16, 16, float> acc[2];
    wmma::fill_fragment(acc[0], 0.0f);
    wmma::fill_fragment(acc[1], 0.0f);

    const int row = tid >> 2;            // staging row 0..63
    const int seg = (tid & 3) * 16;      // 16 bf16 per thread per array

    for (int k0 = 0; k0 < K; k0 += KC) {
        __syncthreads();   // previous iteration's fragment reads done
        {
            const uint4* a_h = reinterpret_cast<const uint4*>(Ah + (size_t)(mb*64 + row)*K + k0 + seg);
            const uint4* a_l = reinterpret_cast<const uint4*>(Al + (size_t)(mb*64 + row)*K + k0 + seg);
            const uint4* b_h = reinterpret_cast<const uint4*>(Bh + (size_t)(nb*64 + row)*K + k0 + seg);
            const uint4* b_l = reinterpret_cast<const uint4*>(Bl + (size_t)(nb*64 + row)*K + k0 + seg);
            uint4* dA_h = reinterpret_cast<uint4*>(sAh + row*LDS2 + seg);
            uint4* dA_l = reinterpret_cast<uint4*>(sAl + row*LDS2 + seg);
            uint4* dB_h = reinterpret_cast<uint4*>(sBh + row*LDS2 + seg);
            uint4* dB_l = reinterpret_cast<uint4*>(sBl + row*LDS2 + seg);
            dA_h[0] = a_h[0]; dA_h[1] = a_h[1];
            dA_l[0] = a_l[0]; dA_l[1] = a_l[1];
            dB_h[0] = b_h[0]; dB_h[1] = b_h[1];
            dB_l[0] = b_l[0]; dB_l[1] = b_l[1];
        }
        __syncthreads();

#pragma unroll
        for (int kk = 0; kk < KC / 16; ++kk) {
            wmma::fragment<wmma::matrix_a, 16, 16, 16, __nv_bfloat16, wmma::row_major> fa_h, fa_l;
            wmma::load_matrix_sync(fa_h, sAh + (wr*16)*LDS2 + kk*16, LDS2);
            wmma::load_matrix_sync(fa_l, sAl + (wr*16)*LDS2 + kk*16, LDS2);
#pragma unroll
            for (int ns = 0; ns < 2; ++ns) {
                wmma::fragment<wmma::matrix_b, 16, 16, 16, __nv_bfloat16, wmma::col_major> fb_h, fb_l;
                wmma::load_matrix_sync(fb_h, sBh + (wc*32 + ns*16)*LDS2 + kk*16, LDS2);
                wmma::load_matrix_sync(fb_l, sBl + (wc*32 + ns*16)*LDS2 + kk*16, LDS2);
                wmma::mma_sync(acc[ns], fa_h, fb_h, acc[ns]);
                wmma::mma_sync(acc[ns], fa_h, fb_l, acc[ns]);
                wmma::mma_sync(acc[ns], fa_l, fb_h, acc[ns]);
            }
        }
    }

    // Epilogue: accum -> smem -> bias add -> scatter to g_xb[t][b][h].
    __syncthreads();
    float* Cs = reinterpret_cast<float*>(raw);     // 64 x LDS2 floats (18.4KB)
    wmma::store_matrix_sync(Cs + (wr*16)*LDS2 + wc*32 + 0,  acc[0], LDS2, wmma::mem_row_major);
    wmma::store_matrix_sync(Cs + (wr*16)*LDS2 + wc*32 + 16, acc[1], LDS2, wmma::mem_row_major);
    __syncthreads();

    const int col4 = (tid & 15) * 4;
    const int n0   = nb * 64 + col4;
    float4 bias;
    bias.x = b1[n0 + 0] + b2[n0 + 0];
    bias.y = b1[n0 + 1] + b2[n0 + 1];
    bias.z = b1[n0 + 2] + b2[n0 + 2];
    bias.w = b1[n0 + 3] + b2[n0 + 3];

#pragma unroll
    for (int rr = 0; rr < 4; ++rr) {
        int r  = rr * 16 + (tid >> 4);
        int m  = mb * 64 + r;
        int b_ = m >> 9;            // / TT
        int t_ = m & (TT - 1);
        float4 o;
        o.x = Cs[r * LDS2 + col4 + 0] + bias.x;
        o.y = Cs[r * LDS2 + col4 + 1] + bias.y;
        o.z = Cs[r * LDS2 + col4 + 2] + bias.z;
        o.w = Cs[r * LDS2 + col4 + 3] + bias.w;
        *reinterpret_cast<float4*>(&g_xb[((size_t)t_ * BB + b_) * HH + n0]) = o;
    }
}

// ------------------------------ helpers -------------------------------------
__device__ __forceinline__ uint32_t smem_u32(const void* p) {
    uint32_t a;
    asm("{ .reg .u64 t; cvta.to.shared.u64 t, %1; cvt.u32.u64 %0, t; }"
        : "=r"(a) : "l"(p));
    return a;
}

__device__ __forceinline__ void mbar_wait(uint32_t mbar, uint32_t parity) {
    asm volatile(
        "{\n\t"
        ".reg .pred P;\n\t"
        "WL%=:\n\t"
        "mbarrier.try_wait.parity.acquire.cluster.shared::cta.b64 P, [%0], %1;\n\t"
        "@!P bra WL%=;\n\t"
        "}"
        :: "r"(mbar), "r"(parity) : "memory");
}

// ------------------------------ recurrence (R3, minus trailing barrier) -----
// smem floats: Wt[512*64] | hb[2][512]f4 | red[16][256] | mbar u64[2]
#define SM_W    (HH*CPG)
#define SM_HB   (SM_W)
#define SM_RED  (SM_W + 2*BPG*HH)
#define SM_MBAR (SM_RED + 16*256)
#define REC_SMEM_BYTES ((SM_MBAR + 8) * 4)

#define STEP_TX (GC * 256 * 4)           // 8192 bytes per phase

__global__ void __launch_bounds__(THR, 1) __cluster_dims__(GC, 1, 1)
rnn_rec(const float* __restrict__ Whh,
        const float* __restrict__ h0,
        float* __restrict__ out_param,
        float* __restrict__ hn,
        int use_g0out)
{
    extern __shared__ float sm[];
    float* Wt  = sm;                 // [k][c]
    float* hb0 = sm + SM_HB;         // [b][k]
    float* hb1 = hb0 + BPG * HH;
    float* red = sm + SM_RED;        // [16][256]
    uint64_t* mbar = reinterpret_cast<uint64_t*>(sm + SM_MBAR);

    const int tid = threadIdx.x;
    uint32_t cg;
    asm("mov.u32 %0, %%cluster_ctarank;" : "=r"(cg));
    const int bg  = blockIdx.x >> 3;
    const int c0  = (int)cg * CPG;
    const int b0  = bg * BPG;
    const int ks  = tid >> 4;
    const int cq  = tid & 15;
    const int ob  = tid >> 6;
    const int oc  = tid & 63;

    float* outp = use_g0out ? g_out0 : out_param;

    const uint32_t mbar_u0 = smem_u32(&mbar[0]);
    const uint32_t mbar_u1 = smem_u32(&mbar[1]);
    const uint32_t hb_u0   = smem_u32(hb0);
    const uint32_t hb_u1   = smem_u32(hb1);

    for (int idx = tid; idx < CPG * (HH / 4); idx += 256) {
        int c  = idx & (CPG - 1);
        int k4 = idx >> 6;
        float4 w = *reinterpret_cast<const float4*>(Whh + (size_t)(c0 + c) * HH + k4 * 4);
        Wt[(k4 * 4 + 0) * CPG + c] = w.x;
        Wt[(k4 * 4 + 1) * CPG + c] = w.y;
        Wt[(k4 * 4 + 2) * CPG + c] = w.z;
        Wt[(k4 * 4 + 3) * CPG + c] = w.w;
    }
    {
        float4* d = reinterpret_cast<float4*>(hb0);
        const float4* s = reinterpret_cast<const float4*>(h0 + (size_t)b0 * HH);
        d[tid]       = s[tid];
        d[tid + 256] = s[tid + 256];
    }
    if (tid == 0) {
        asm volatile("mbarrier.init.shared.b64 [%0], %1;" :: "r"(mbar_u0), "r"(1u) : "memory");
        asm volatile("mbarrier.init.shared.b64 [%0], %1;" :: "r"(mbar_u1), "r"(1u) : "memory");
        asm volatile("mbarrier.arrive.expect_tx.shared.b64 _, [%0], %1;"
                     :: "r"(mbar_u0), "r"((unsigned)STEP_TX) : "memory");
        asm volatile("mbarrier.arrive.expect_tx.shared.b64 _, [%0], %1;"
                     :: "r"(mbar_u1), "r"((unsigned)STEP_TX) : "memory");
    }
    __syncthreads();
    asm volatile("barrier.cluster.arrive.aligned;" ::: "memory");
    asm volatile("barrier.cluster.wait.aligned;"   ::: "memory");

    uint32_t ph0 = 0, ph1 = 0;
    const uint32_t my_off = (uint32_t)((ob * HH + c0 + oc) * 4);

    for (int t = 0; t < TT; ++t) {
        const int p = t & 1;
        float xbv = __ldcg(&g_xb[((size_t)t * BB + (b0 + ob)) * HH + c0 + oc]);

        if (t > 0) {
            if (p) { mbar_wait(mbar_u1, ph1); ph1 ^= 1; }
            else   { mbar_wait(mbar_u0, ph0); ph0 ^= 1; }
            if (tid == 0) {
                uint32_t mu = p ? mbar_u1 : mbar_u0;
                asm volatile("mbarrier.arrive.expect_tx.shared.b64 _, [%0], %1;"
                             :: "r"(mu), "r"((unsigned)STEP_TX) : "memory");
            }
        }

        const float* hb = p ? hb1 : hb0;

        float acc[4][4];
#pragma unroll
        for (int i = 0; i < 4; i++)
#pragma unroll
            for (int j = 0; j < 4; j++) acc[i][j] = 0.f;

        const int kb = ks * 32;
#pragma unroll
        for (int kc = 0; kc < 32; kc += 4) {
            const int k = kb + kc;
            float4 hv[4];
#pragma unroll
            for (int b = 0; b < 4; b++)
                hv[b] = *reinterpret_cast<const float4*>(&hb[b * HH + k]);
#pragma unroll
            for (int kk = 0; kk < 4; kk++) {
                float4 w4 = *reinterpret_cast<const float4*>(&Wt[(k + kk) * CPG + cq * 4]);
                float wj[4] = {w4.x, w4.y, w4.z, w4.w};
                float hk[4] = {hv[0].x, hv[1].x, hv[2].x, hv[3].x};
                if (kk == 1) { hk[0]=hv[0].y; hk[1]=hv[1].y; hk[2]=hv[2].y; hk[3]=hv[3].y; }
                if (kk == 2) { hk[0]=hv[0].z; hk[1]=hv[1].z; hk[2]=hv[2].z; hk[3]=hv[3].z; }
                if (kk == 3) { hk[0]=hv[0].w; hk[1]=hv[1].w; hk[2]=hv[2].w; hk[3]=hv[3].w; }
#pragma unroll
                for (int b = 0; b < 4; b++)
#pragma unroll
                    for (int j = 0; j < 4; j++)
                        acc[b][j] += hk[b] * wj[j];
            }
        }

#pragma unroll
        for (int b = 0; b < 4; ++b)
            *reinterpret_cast<float4*>(&red[ks * 256 + b * 64 + cq * 4]) =
                make_float4(acc[b][0], acc[b][1], acc[b][2], acc[b][3]);
        __syncthreads();   // S1

        float s = 0.f;
#pragma unroll
        for (int k2 = 0; k2 < 16; ++k2) s += red[k2 * 256 + tid];
        float v = tanhf(s + xbv);

        outp[((size_t)(b0 + ob) * TT + t) * HH + c0 + oc] = v;
        if (t == TT - 1) hn[(size_t)(b0 + ob) * HH + c0 + oc] = v;

        if (t < TT - 1) {
            const uint32_t dst_l  = (p ? hb_u0 : hb_u1) + my_off;
            const uint32_t mbar_l = p ? mbar_u0 : mbar_u1;
            const uint32_t vb = __float_as_uint(v);
#pragma unroll
            for (int r = 0; r < GC; r++) {
                uint32_t da, ma;
                asm("mapa.shared::cluster.u32 %0, %1, %2;" : "=r"(da) : "r"(dst_l),  "r"(r));
                asm("mapa.shared::cluster.u32 %0, %1, %2;" : "=r"(ma) : "r"(mbar_l), "r"(r));
                asm volatile(
                    "st.async.shared::cluster.mbarrier::complete_tx::bytes.b32 [%0], %1, [%2];"
                    :: "r"(da), "r"(vb), "r"(ma) : "memory");
            }
        }
        // Trailing __syncthreads removed: red reuse at t+1 is ordered by the
        // t+1 mbar wait (needs ALL sends, each data-dependent on red reads).
    }

    asm volatile("barrier.cluster.arrive.aligned;" ::: "memory");
    asm volatile("barrier.cluster.wait.aligned;"   ::: "memory");
}

// ------------------------------ launch --------------------------------------
extern "C" void kernel_launch(void* const* d_in, const int* in_sizes, int n_in,
                              void* d_out, int out_size)
{
    const float* x    = (const float*)d_in[0];
    const float* h0   = (const float*)d_in[1];   // [2, B, H]
    const float* Wih0 = (const float*)d_in[2];
    const float* Whh0 = (const float*)d_in[3];
    const float* bih0 = (const float*)d_in[4];
    const float* bhh0 = (const float*)d_in[5];
    const float* Wih1 = (const float*)d_in[6];
    const float* Whh1 = (const float*)d_in[7];
    const float* bih1 = (const float*)d_in[8];
    const float* bhh1 = (const float*)d_in[9];

    float* out  = (float*)d_out;
    float* out1 = out;                       // [B,T,H]
    float* hn0  = out + (size_t)BTH;         // h_n[0]
    float* hn1  = hn0 + (size_t)BB * HH;     // h_n[1]

    static int smem_set = 0;
    if (!smem_set) {
        cudaFuncSetAttribute(rnn_rec, cudaFuncAttributeMaxDynamicSharedMemorySize,
                             REC_SMEM_BYTES);
        smem_set = 1;
    }

    __nv_bfloat16 *ahi, *alo, *whi, *wlo;
    cudaGetSymbolAddress((void**)&ahi, g_ahi);
    cudaGetSymbolAddress((void**)&alo, g_alo);
    cudaGetSymbolAddress((void**)&whi, g_whi);
    cudaGetSymbolAddress((void**)&wlo, g_wlo);
    float* out0p;
    cudaGetSymbolAddress((void**)&out0p, g_out0);

    dim3 ggrid(HH / 64, (BB * TT) / 64);     // (8, 512)

    // ---- layer 0 ----
    conv_split<<<(HH*IDIM + 255)/256, 256>>>(Wih0, whi, wlo, HH*IDIM);
    conv_split<<<(BB*TT*IDIM + 255)/256, 256>>>(x, ahi, alo, BB*TT*IDIM);
    gemm_wmma<<<ggrid, 256>>>(ahi, alo, whi, wlo, bih0, bhh0, IDIM);
    rnn_rec<<<NCTA, THR, REC_SMEM_BYTES>>>(Whh0, h0, nullptr, hn0, 1);

    // ---- layer 1 ----
    conv_split<<<(HH*HH + 255)/256, 256>>>(Wih1, whi, wlo, HH*HH);
    conv_split<<<(BTH + 255)/256, 256>>>(out0p, ahi, alo, BTH);
    gemm_wmma<<<ggrid, 256>>>(ahi, alo, whi, wlo, bih1, bhh1, HH);
    rnn_rec<<<NCTA, THR, REC_SMEM_BYTES>>>(Whh1, h0 + (size_t)BB * HH, out1, hn1, 0);
}

// round 10
// speedup vs baseline: 1.6576x; 1.0145x over previous
#include <cuda_runtime.h>
#include <cuda_bf16.h>
#include <mma.h>
#include <cstdint>

using namespace nvcuda;

// Problem dims (fixed)
#define BB   64
#define TT   512
#define IDIM 256
#define HH   512
#define BTH  (BB*TT*HH)

// Recurrence decomposition: 16 clusters (batch groups) x 8 CTAs (column groups)
#define GB   16
#define GC   8
#define BPG  4
#define CPG  64
#define NCTA (GB*GC)
#define THR  256

// ------------------------------ scratch ------------------------------------
__device__ float g_xb[TT*BB*HH];              // input projection [t][b][h]
__device__ __nv_bfloat16 g_ahi[BTH];          // layer-0 output, split hi
__device__ __nv_bfloat16 g_alo[BTH];          // layer-0 output, split lo
__device__ __nv_bfloat16 g_whi[HH*HH];        // W_ih split hi
__device__ __nv_bfloat16 g_wlo[HH*HH];        // W_ih split lo

// ------------------------------ split conversion (weights only) --------------
__global__ void conv_split(const float* __restrict__ s,
                           __nv_bfloat16* __restrict__ hi,
                           __nv_bfloat16* __restrict__ lo, int n)
{
    int i = blockIdx.x * blockDim.x + threadIdx.x;
    if (i < n) {
        float x = s[i];
        __nv_bfloat16 h = __float2bfloat16_rn(x);
        hi[i] = h;
        lo[i] = __float2bfloat16_rn(x - __bfloat162float(h));
    }
}

// ------------------------------ wmma GEMM (bf16 x3 split, fused A split) -----
// Y[t][b][n] = sum_k A[m][k]*W[n][k] + b1[n] + b2[n],  m = b*TT + t
// mode 0: A read as fp32 (Afp), hi/lo split done during smem staging.
// mode 1: A read from pre-split bf16 arrays (Ah/Al).
#define KC   64
#define LDS2 72

__global__ void __launch_bounds__(256) gemm_wmma(
    const float* __restrict__ Afp,
    const __nv_bfloat16* __restrict__ Ah, const __nv_bfloat16* __restrict__ Al,
    const __nv_bfloat16* __restrict__ Bh, const __nv_bfloat16* __restrict__ Bl,
    const float* __restrict__ b1, const float* __restrict__ b2,
    int K, int mode)
{
    __shared__ char raw[4 * 64 * LDS2 * 2];   // 36864 B
    __nv_bfloat16* sAh = reinterpret_cast<__nv_bfloat16*>(raw);
    __nv_bfloat16* sAl = sAh + 64 * LDS2;
    __nv_bfloat16* sBh = sAl + 64 * LDS2;
    __nv_bfloat16* sBl = sBh + 64 * LDS2;

    const int tid = threadIdx.x;
    const int nb  = blockIdx.x;
    const int mb  = blockIdx.y;
    const int wid = tid >> 5;
    const int wr  = wid & 3;
    const int wc  = wid >> 2;

    wmma::fragment<wmma::accumulator, 16, 16, 16, float> acc[2];
    wmma::fill_fragment(acc[0], 0.0f);
    wmma::fill_fragment(acc[1], 0.0f);

    const int row = tid >> 2;            // 0..63
    const int seg = (tid & 3) * 16;      // 16 elems per thread

    for (int k0 = 0; k0 < K; k0 += KC) {
        __syncthreads();
        // ---- stage A ----
        if (mode == 0) {
            const float4* src = reinterpret_cast<const float4*>(
                Afp + (size_t)(mb*64 + row)*K + k0 + seg);
            float v[16];
#pragma unroll
            for (int j = 0; j < 4; ++j) {
                float4 f = src[j];
                v[j*4+0] = f.x; v[j*4+1] = f.y; v[j*4+2] = f.z; v[j*4+3] = f.w;
            }
            uint32_t ph[8], pl[8];
#pragma unroll
            for (int i = 0; i < 8; ++i) {
                __nv_bfloat16 h0b = __float2bfloat16_rn(v[2*i]);
                __nv_bfloat16 h1b = __float2bfloat16_rn(v[2*i+1]);
                __nv_bfloat16 l0b = __float2bfloat16_rn(v[2*i]   - __bfloat162float(h0b));
                __nv_bfloat16 l1b = __float2bfloat16_rn(v[2*i+1] - __bfloat162float(h1b));
                ph[i] = (uint32_t)__bfloat16_as_ushort(h0b) |
                        ((uint32_t)__bfloat16_as_ushort(h1b) << 16);
                pl[i] = (uint32_t)__bfloat16_as_ushort(l0b) |
                        ((uint32_t)__bfloat16_as_ushort(l1b) << 16);
            }
            uint4* dH = reinterpret_cast<uint4*>(sAh + row*LDS2 + seg);
            uint4* dL = reinterpret_cast<uint4*>(sAl + row*LDS2 + seg);
            dH[0] = make_uint4(ph[0],ph[1],ph[2],ph[3]);
            dH[1] = make_uint4(ph[4],ph[5],ph[6],ph[7]);
            dL[0] = make_uint4(pl[0],pl[1],pl[2],pl[3]);
            dL[1] = make_uint4(pl[4],pl[5],pl[6],pl[7]);
        } else {
            const uint4* a_h = reinterpret_cast<const uint4*>(Ah + (size_t)(mb*64 + row)*K + k0 + seg);
            const uint4* a_l = reinterpret_cast<const uint4*>(Al + (size_t)(mb*64 + row)*K + k0 + seg);
            uint4* dH = reinterpret_cast<uint4*>(sAh + row*LDS2 + seg);
            uint4* dL = reinterpret_cast<uint4*>(sAl + row*LDS2 + seg);
            dH[0] = a_h[0]; dH[1] = a_h[1];
            dL[0] = a_l[0]; dL[1] = a_l[1];
        }
        // ---- stage B (always pre-split) ----
        {
            const uint4* b_h = reinterpret_cast<const uint4*>(Bh + (size_t)(nb*64 + row)*K + k0 + seg);
            const uint4* b_l = reinterpret_cast<const uint4*>(Bl + (size_t)(nb*64 + row)*K + k0 + seg);
            uint4* dH = reinterpret_cast<uint4*>(sBh + row*LDS2 + seg);
            uint4* dL = reinterpret_cast<uint4*>(sBl + row*LDS2 + seg);
            dH[0] = b_h[0]; dH[1] = b_h[1];
            dL[0] = b_l[0]; dL[1] = b_l[1];
        }
        __syncthreads();

#pragma unroll
        for (int kk = 0; kk < KC / 16; ++kk) {
            wmma::fragment<wmma::matrix_a, 16, 16, 16, __nv_bfloat16, wmma::row_major> fa_h, fa_l;
            wmma::load_matrix_sync(fa_h, sAh + (wr*16)*LDS2 + kk*16, LDS2);
            wmma::load_matrix_sync(fa_l, sAl + (wr*16)*LDS2 + kk*16, LDS2);
#pragma unroll
            for (int ns = 0; ns < 2; ++ns) {
                wmma::fragment<wmma::matrix_b, 16, 16, 16, __nv_bfloat16, wmma::col_major> fb_h, fb_l;
                wmma::load_matrix_sync(fb_h, sBh + (wc*32 + ns*16)*LDS2 + kk*16, LDS2);
                wmma::load_matrix_sync(fb_l, sBl + (wc*32 + ns*16)*LDS2 + kk*16, LDS2);
                wmma::mma_sync(acc[ns], fa_h, fb_h, acc[ns]);
                wmma::mma_sync(acc[ns], fa_h, fb_l, acc[ns]);
                wmma::mma_sync(acc[ns], fa_l, fb_h, acc[ns]);
            }
        }
    }

    __syncthreads();
    float* Cs = reinterpret_cast<float*>(raw);
    wmma::store_matrix_sync(Cs + (wr*16)*LDS2 + wc*32 + 0,  acc[0], LDS2, wmma::mem_row_major);
    wmma::store_matrix_sync(Cs + (wr*16)*LDS2 + wc*32 + 16, acc[1], LDS2, wmma::mem_row_major);
    __syncthreads();

    const int col4 = (tid & 15) * 4;
    const int n0   = nb * 64 + col4;
    float4 bias;
    bias.x = b1[n0 + 0] + b2[n0 + 0];
    bias.y = b1[n0 + 1] + b2[n0 + 1];
    bias.z = b1[n0 + 2] + b2[n0 + 2];
    bias.w = b1[n0 + 3] + b2[n0 + 3];

#pragma unroll
    for (int rr = 0; rr < 4; ++rr) {
        int r  = rr * 16 + (tid >> 4);
        int m  = mb * 64 + r;
        int b_ = m >> 9;
        int t_ = m & (TT - 1);
        float4 o;
        o.x = Cs[r * LDS2 + col4 + 0] + bias.x;
        o.y = Cs[r * LDS2 + col4 + 1] + bias.y;
        o.z = Cs[r * LDS2 + col4 + 2] + bias.z;
        o.w = Cs[r * LDS2 + col4 + 3] + bias.w;
        *reinterpret_cast<float4*>(&g_xb[((size_t)t_ * BB + b_) * HH + n0]) = o;
    }
}

// ------------------------------ helpers -------------------------------------
__device__ __forceinline__ uint32_t smem_u32(const void* p) {
    uint32_t a;
    asm("{ .reg .u64 t; cvta.to.shared.u64 t, %1; cvt.u32.u64 %0, t; }"
        : "=r"(a) : "l"(p));
    return a;
}

__device__ __forceinline__ void mbar_wait(uint32_t mbar, uint32_t parity) {
    asm volatile(
        "{\n\t"
        ".reg .pred P;\n\t"
        "WL%=:\n\t"
        "mbarrier.try_wait.parity.acquire.cluster.shared::cta.b64 P, [%0], %1;\n\t"
        "@!P bra WL%=;\n\t"
        "}"
        :: "r"(mbar), "r"(parity) : "memory");
}

// ------------------------------ recurrence (R9 core; layer-0 writes bf16 split)
#define SM_W    (HH*CPG)
#define SM_HB   (SM_W)
#define SM_RED  (SM_W + 2*BPG*HH)
#define SM_MBAR (SM_RED + 16*256)
#define REC_SMEM_BYTES ((SM_MBAR + 8) * 4)

#define STEP_TX (GC * 256 * 4)

__global__ void __launch_bounds__(THR, 1) __cluster_dims__(GC, 1, 1)
rnn_rec(const float* __restrict__ Whh,
        const float* __restrict__ h0,
        float* __restrict__ out_param,
        float* __restrict__ hn,
        int use_g0out)
{
    extern __shared__ float sm[];
    float* Wt  = sm;
    float* hb0 = sm + SM_HB;
    float* hb1 = hb0 + BPG * HH;
    float* red = sm + SM_RED;
    uint64_t* mbar = reinterpret_cast<uint64_t*>(sm + SM_MBAR);

    const int tid = threadIdx.x;
    uint32_t cg;
    asm("mov.u32 %0, %%cluster_ctarank;" : "=r"(cg));
    const int bg  = blockIdx.x >> 3;
    const int c0  = (int)cg * CPG;
    const int b0  = bg * BPG;
    const int ks  = tid >> 4;
    const int cq  = tid & 15;
    const int ob  = tid >> 6;
    const int oc  = tid & 63;

    const uint32_t mbar_u0 = smem_u32(&mbar[0]);
    const uint32_t mbar_u1 = smem_u32(&mbar[1]);
    const uint32_t hb_u0   = smem_u32(hb0);
    const uint32_t hb_u1   = smem_u32(hb1);

    for (int idx = tid; idx < CPG * (HH / 4); idx += 256) {
        int c  = idx & (CPG - 1);
        int k4 = idx >> 6;
        float4 w = *reinterpret_cast<const float4*>(Whh + (size_t)(c0 + c) * HH + k4 * 4);
        Wt[(k4 * 4 + 0) * CPG + c] = w.x;
        Wt[(k4 * 4 + 1) * CPG + c] = w.y;
        Wt[(k4 * 4 + 2) * CPG + c] = w.z;
        Wt[(k4 * 4 + 3) * CPG + c] = w.w;
    }
    {
        float4* d = reinterpret_cast<float4*>(hb0);
        const float4* s = reinterpret_cast<const float4*>(h0 + (size_t)b0 * HH);
        d[tid]       = s[tid];
        d[tid + 256] = s[tid + 256];
    }
    if (tid == 0) {
        asm volatile("mbarrier.init.shared.b64 [%0], %1;" :: "r"(mbar_u0), "r"(1u) : "memory");
        asm volatile("mbarrier.init.shared.b64 [%0], %1;" :: "r"(mbar_u1), "r"(1u) : "memory");
        asm volatile("mbarrier.arrive.expect_tx.shared.b64 _, [%0], %1;"
                     :: "r"(mbar_u0), "r"((unsigned)STEP_TX) : "memory");
        asm volatile("mbarrier.arrive.expect_tx.shared.b64 _, [%0], %1;"
                     :: "r"(mbar_u1), "r"((unsigned)STEP_TX) : "memory");
    }
    __syncthreads();
    asm volatile("barrier.cluster.arrive.aligned;" ::: "memory");
    asm volatile("barrier.cluster.wait.aligned;"   ::: "memory");

    uint32_t ph0 = 0, ph1 = 0;
    const uint32_t my_off = (uint32_t)((ob * HH + c0 + oc) * 4);

    for (int t = 0; t < TT; ++t) {
        const int p = t & 1;
        float xbv = __ldcg(&g_xb[((size_t)t * BB + (b0 + ob)) * HH + c0 + oc]);

        if (t > 0) {
            if (p) { mbar_wait(mbar_u1, ph1); ph1 ^= 1; }
            else   { mbar_wait(mbar_u0, ph0); ph0 ^= 1; }
            if (tid == 0) {
                uint32_t mu = p ? mbar_u1 : mbar_u0;
                asm volatile("mbarrier.arrive.expect_tx.shared.b64 _, [%0], %1;"
                             :: "r"(mu), "r"((unsigned)STEP_TX) : "memory");
            }
        }

        const float* hb = p ? hb1 : hb0;

        float acc[4][4];
#pragma unroll
        for (int i = 0; i < 4; i++)
#pragma unroll
            for (int j = 0; j < 4; j++) acc[i][j] = 0.f;

        const int kb = ks * 32;
#pragma unroll
        for (int kc = 0; kc < 32; kc += 4) {
            const int k = kb + kc;
            float4 hv[4];
#pragma unroll
            for (int b = 0; b < 4; b++)
                hv[b] = *reinterpret_cast<const float4*>(&hb[b * HH + k]);
#pragma unroll
            for (int kk = 0; kk < 4; kk++) {
                float4 w4 = *reinterpret_cast<const float4*>(&Wt[(k + kk) * CPG + cq * 4]);
                float wj[4] = {w4.x, w4.y, w4.z, w4.w};
                float hk[4] = {hv[0].x, hv[1].x, hv[2].x, hv[3].x};
                if (kk == 1) { hk[0]=hv[0].y; hk[1]=hv[1].y; hk[2]=hv[2].y; hk[3]=hv[3].y; }
                if (kk == 2) { hk[0]=hv[0].z; hk[1]=hv[1].z; hk[2]=hv[2].z; hk[3]=hv[3].z; }
                if (kk == 3) { hk[0]=hv[0].w; hk[1]=hv[1].w; hk[2]=hv[2].w; hk[3]=hv[3].w; }
#pragma unroll
                for (int b = 0; b < 4; b++)
#pragma unroll
                    for (int j = 0; j < 4; j++)
                        acc[b][j] += hk[b] * wj[j];
            }
        }

#pragma unroll
        for (int b = 0; b < 4; ++b)
            *reinterpret_cast<float4*>(&red[ks * 256 + b * 64 + cq * 4]) =
                make_float4(acc[b][0], acc[b][1], acc[b][2], acc[b][3]);
        __syncthreads();   // S1

        float s = 0.f;
#pragma unroll
        for (int k2 = 0; k2 < 16; ++k2) s += red[k2 * 256 + tid];
        float v = tanhf(s + xbv);

        const size_t oidx = ((size_t)(b0 + ob) * TT + t) * HH + c0 + oc;
        if (use_g0out) {
            // layer 0: write output directly as bf16 hi/lo split (gemm1 input)
            __nv_bfloat16 hb16 = __float2bfloat16_rn(v);
            g_ahi[oidx] = hb16;
            g_alo[oidx] = __float2bfloat16_rn(v - __bfloat162float(hb16));
        } else {
            out_param[oidx] = v;
        }
        if (t == TT - 1) hn[(size_t)(b0 + ob) * HH + c0 + oc] = v;

        if (t < TT - 1) {
            const uint32_t dst_l  = (p ? hb_u0 : hb_u1) + my_off;
            const uint32_t mbar_l = p ? mbar_u0 : mbar_u1;
            const uint32_t vb = __float_as_uint(v);
#pragma unroll
            for (int r = 0; r < GC; r++) {
                uint32_t da, ma;
                asm("mapa.shared::cluster.u32 %0, %1, %2;" : "=r"(da) : "r"(dst_l),  "r"(r));
                asm("mapa.shared::cluster.u32 %0, %1, %2;" : "=r"(ma) : "r"(mbar_l), "r"(r));
                asm volatile(
                    "st.async.shared::cluster.mbarrier::complete_tx::bytes.b32 [%0], %1, [%2];"
                    :: "r"(da), "r"(vb), "r"(ma) : "memory");
            }
        }
    }

    asm volatile("barrier.cluster.arrive.aligned;" ::: "memory");
    asm volatile("barrier.cluster.wait.aligned;"   ::: "memory");
}

// ------------------------------ launch --------------------------------------
extern "C" void kernel_launch(void* const* d_in, const int* in_sizes, int n_in,
                              void* d_out, int out_size)
{
    const float* x    = (const float*)d_in[0];
    const float* h0   = (const float*)d_in[1];
    const float* Wih0 = (const float*)d_in[2];
    const float* Whh0 = (const float*)d_in[3];
    const float* bih0 = (const float*)d_in[4];
    const float* bhh0 = (const float*)d_in[5];
    const float* Wih1 = (const float*)d_in[6];
    const float* Whh1 = (const float*)d_in[7];
    const float* bih1 = (const float*)d_in[8];
    const float* bhh1 = (const float*)d_in[9];

    float* out  = (float*)d_out;
    float* out1 = out;                       // [B,T,H]
    float* hn0  = out + (size_t)BTH;
    float* hn1  = hn0 + (size_t)BB * HH;

    static int smem_set = 0;
    if (!smem_set) {
        cudaFuncSetAttribute(rnn_rec, cudaFuncAttributeMaxDynamicSharedMemorySize,
                             REC_SMEM_BYTES);
        smem_set = 1;
    }

    __nv_bfloat16 *ahi, *alo, *whi, *wlo;
    cudaGetSymbolAddress((void**)&ahi, g_ahi);
    cudaGetSymbolAddress((void**)&alo, g_alo);
    cudaGetSymbolAddress((void**)&whi, g_whi);
    cudaGetSymbolAddress((void**)&wlo, g_wlo);

    dim3 ggrid(HH / 64, (BB * TT) / 64);     // (8, 512)

    // ---- layer 0 ----
    conv_split<<<(HH*IDIM + 255)/256, 256>>>(Wih0, whi, wlo, HH*IDIM);
    gemm_wmma<<<ggrid, 256>>>(x, nullptr, nullptr, whi, wlo, bih0, bhh0, IDIM, 0);
    rnn_rec<<<NCTA, THR, REC_SMEM_BYTES>>>(Whh0, h0, out1, hn0, 1);

    // ---- layer 1 ----
    conv_split<<<(HH*HH + 255)/256, 256>>>(Wih1, whi, wlo, HH*HH);
    gemm_wmma<<<ggrid, 256>>>(nullptr, ahi, alo, whi, wlo, bih1, bhh1, HH, 1);
    rnn_rec<<<NCTA, THR, REC_SMEM_BYTES>>>(Whh1, h0 + (size_t)BB * HH, out1, hn1, 0);
}